// round 1
// baseline (speedup 1.0000x reference)
#include <cuda_runtime.h>
#include <math.h>

// Problem constants (match reference)
#define Vocab 100000
#define Dim   256
#define Bb    32
#define Nn    128
#define Kk    100
#define NTOK  (Bb * Nn)            // 4096 tokens
#define ROWS  (Kk + 1)             // 101 gathered rows per token
#define NORM_TERM 11.512925f
#define LOG_K     4.6051702f       // log(100)
#define INV_NTOK  (1.0f / 4096.0f)

__device__ __forceinline__ float softplusf(float x) {
    // log1p(exp(x)), numerically stable
    if (x > 0.0f) return x + log1pf(expf(-x));
    return log1pf(expf(x));
}

__global__ void zero_out_kernel(float* out) {
    out[0] = 0.0f;
}

__global__ __launch_bounds__(256, 8)
void nce_loss_kernel(const int* __restrict__ target,        // (B,N)
                     const int* __restrict__ noise,         // (B,N,K)
                     const float* __restrict__ hidden,      // (B,N,D)
                     const float* __restrict__ weight,      // (V,D)
                     const float* __restrict__ bias,        // (V,)
                     const float* __restrict__ noise_probs, // (V,)
                     float* __restrict__ out)
{
    const int token = blockIdx.x;          // 0 .. NTOK-1
    const int tid   = threadIdx.x;
    const int lane  = tid & 31;
    const int warp  = tid >> 5;            // 0..7

    __shared__ float hsh[Dim];
    hsh[tid] = hidden[(size_t)token * Dim + tid];
    __syncthreads();

    // Each lane caches the hidden elements it will multiply:
    // weight row viewed as 64 float4; lane handles chunks [lane] and [32+lane].
    const float4* hv4 = reinterpret_cast<const float4*>(hsh);
    const float4 h0 = hv4[lane];
    const float4 h1 = hv4[32 + lane];

    float local = 0.0f;

    for (int r = warp; r < ROWS; r += 8) {
        const bool is_target = (r == 0);
        const int id = is_target ? target[token]
                                 : noise[(size_t)token * Kk + (r - 1)];
        const float4* wrow = reinterpret_cast<const float4*>(weight + (size_t)id * Dim);
        const float4 w0 = wrow[lane];
        const float4 w1 = wrow[32 + lane];

        float s = h0.x * w0.x + h0.y * w0.y + h0.z * w0.z + h0.w * w0.w
                + h1.x * w1.x + h1.y * w1.y + h1.z * w1.z + h1.w * w1.w;

        // warp reduce
        #pragma unroll
        for (int o = 16; o > 0; o >>= 1)
            s += __shfl_xor_sync(0xFFFFFFFFu, s, o);

        if (lane == 0) {
            const float score = s + bias[id] - NORM_TERM;
            if (is_target) {
                const float logit_true = score - LOG_K;
                local += softplusf(-logit_true);
            } else {
                const float score_noise = logf(noise_probs[id]);
                const float logit_noise = score - score_noise - LOG_K;
                local += softplusf(logit_noise);
            }
        }
    }

    // block reduce (lane 0 of each of 8 warps holds a partial)
    __shared__ float wsum[8];
    if (lane == 0) wsum[warp] = local;
    __syncthreads();
    if (tid == 0) {
        float t = 0.0f;
        #pragma unroll
        for (int i = 0; i < 8; i++) t += wsum[i];
        atomicAdd(out, t * INV_NTOK);
    }
}

extern "C" void kernel_launch(void* const* d_in, const int* in_sizes, int n_in,
                              void* d_out, int out_size)
{
    const int*   target      = (const int*)  d_in[0];
    const int*   noise       = (const int*)  d_in[1];
    const float* hidden      = (const float*)d_in[2];
    const float* weight      = (const float*)d_in[3];
    const float* bias        = (const float*)d_in[4];
    const float* noise_probs = (const float*)d_in[5];
    float* out = (float*)d_out;

    zero_out_kernel<<<1, 1>>>(out);
    nce_loss_kernel<<<NTOK, 256>>>(target, noise, hidden, weight, bias,
                                   noise_probs, out);
}

// round 2
// speedup vs baseline: 1.0992x; 1.0992x over previous
#include <cuda_runtime.h>
#include <math.h>

// Problem constants (match reference)
#define Vocab 100000
#define Dim   256
#define Bb    32
#define Nn    128
#define Kk    100
#define NTOK  (Bb * Nn)            // 4096 tokens
#define ROWS  (Kk + 1)             // 101 gathered rows per token
#define NORM_TERM 11.512925f
#define LOG_K     4.6051702f       // log(100)
#define INV_NTOK  (1.0f / 4096.0f)

__device__ __forceinline__ float fast_softplus(float x) {
    // softplus(x) = max(x,0) + log(1 + exp(-|x|)), fast-math version
    float e = __expf(-fabsf(x));
    float l = __logf(1.0f + e);
    return (x > 0.0f) ? x + l : l;
}

__global__ void zero_out_kernel(float* out) {
    out[0] = 0.0f;
}

__global__ __launch_bounds__(256)
void nce_loss_kernel(const int* __restrict__ target,        // (B,N)
                     const int* __restrict__ noise,         // (B,N,K)
                     const float* __restrict__ hidden,      // (B,N,D)
                     const float* __restrict__ weight,      // (V,D)
                     const float* __restrict__ bias,        // (V,)
                     const float* __restrict__ noise_probs, // (V,)
                     float* __restrict__ out)
{
    const int token = blockIdx.x;          // 0 .. NTOK-1
    const int tid   = threadIdx.x;
    const int lane  = tid & 31;
    const int warp  = tid >> 5;            // 0..7
    const int g     = lane >> 3;           // row-group within warp: 0..3
    const int p     = lane & 7;            // position within 8-lane group

    __shared__ float hsh[Dim];
    hsh[tid] = hidden[(size_t)token * Dim + tid];
    __syncthreads();

    // Lane caches its 8 hidden float4 chunks: chunk indices p + 8j (j=0..7).
    // For fixed j, the 8 lanes of a group cover one contiguous 128B line.
    const float4* hv4 = reinterpret_cast<const float4*>(hsh);
    float4 h[8];
    #pragma unroll
    for (int j = 0; j < 8; j++) h[j] = hv4[p + 8 * j];

    const int* noise_tok = noise + (size_t)token * Kk;

    float local = 0.0f;

    // Rows processed per block-iteration: 8 warps * 4 groups = 32.
    // iters: r = warp*4 + g + 32*iter, iter = 0..3 (predicated at r >= 101).
    #pragma unroll
    for (int iter = 0; iter < 4; iter++) {
        const int r = warp * 4 + g + 32 * iter;
        const bool active = (r < ROWS);

        int id = 0;
        if (active)
            id = (r == 0) ? target[token] : noise_tok[r - 1];

        float s = 0.0f;
        if (active) {
            const float4* wv4 =
                reinterpret_cast<const float4*>(weight + (size_t)id * Dim);
            #pragma unroll
            for (int j = 0; j < 8; j++) {
                const float4 w = wv4[p + 8 * j];
                s += h[j].x * w.x + h[j].y * w.y
                   + h[j].z * w.z + h[j].w * w.w;
            }
        }

        // reduce across the 8-lane group (xor offsets stay inside the group)
        s += __shfl_xor_sync(0xFFFFFFFFu, s, 1);
        s += __shfl_xor_sync(0xFFFFFFFFu, s, 2);
        s += __shfl_xor_sync(0xFFFFFFFFu, s, 4);

        if (active && p == 0) {
            const float score = s + bias[id] - NORM_TERM;
            if (r == 0) {
                const float logit_true = score - LOG_K;
                local += fast_softplus(-logit_true);
            } else {
                const float score_noise = __logf(noise_probs[id]);
                local += fast_softplus(score - score_noise - LOG_K);
            }
        }
    }

    // local is nonzero only in lanes 0,8,16,24; full-warp xor reduce is cheap
    #pragma unroll
    for (int o = 16; o > 0; o >>= 1)
        local += __shfl_xor_sync(0xFFFFFFFFu, local, o);

    __shared__ float wsum[8];
    if (lane == 0) wsum[warp] = local;
    __syncthreads();
    if (tid == 0) {
        float t = 0.0f;
        #pragma unroll
        for (int i = 0; i < 8; i++) t += wsum[i];
        atomicAdd(out, t * INV_NTOK);
    }
}

extern "C" void kernel_launch(void* const* d_in, const int* in_sizes, int n_in,
                              void* d_out, int out_size)
{
    const int*   target      = (const int*)  d_in[0];
    const int*   noise       = (const int*)  d_in[1];
    const float* hidden      = (const float*)d_in[2];
    const float* weight      = (const float*)d_in[3];
    const float* bias        = (const float*)d_in[4];
    const float* noise_probs = (const float*)d_in[5];
    float* out = (float*)d_out;

    zero_out_kernel<<<1, 1>>>(out);
    nce_loss_kernel<<<NTOK, 256>>>(target, noise, hidden, weight, bias,
                                   noise_probs, out);
}

// round 6
// speedup vs baseline: 1.2661x; 1.1518x over previous
#include <cuda_runtime.h>
#include <math.h>

#define Vocab 100000
#define Dim   256
#define Bb    32
#define Nn    128
#define Kk    100
#define NTOK  (Bb * Nn)            // 4096 tokens
#define ROWS  (Kk + 1)             // 101 gathered rows per token
#define NORM_TERM 11.512925f
#define LOG_K     4.6051702f       // log(100)
#define INV_NTOK  (1.0f / 4096.0f)

__device__ __forceinline__ float fast_softplus(float x) {
    float e = __expf(-fabsf(x));
    float l = __logf(1.0f + e);
    return (x > 0.0f) ? x + l : l;
}

__global__ void zero_out_kernel(float* out) {
    out[0] = 0.0f;
}

__global__ __launch_bounds__(256, 6)
void nce_loss_kernel(const int* __restrict__ target,        // (B,N)
                     const int* __restrict__ noise,         // (B,N,K)
                     const float* __restrict__ hidden,      // (B,N,D)
                     const float* __restrict__ weight,      // (V,D)
                     const float* __restrict__ bias,        // (V,)
                     const float* __restrict__ noise_probs, // (V,)
                     float* __restrict__ out)
{
    const int token = blockIdx.x;
    const int tid   = threadIdx.x;
    const int lane  = tid & 31;
    const int warp  = tid >> 5;            // 0..7
    const int g     = lane >> 3;           // row-group in warp: 0..3
    const int p     = lane & 7;            // position in 8-lane group

    __shared__ float hsh[Dim];
    __shared__ int   idsh[ROWS + 3];       // padded
    __shared__ float wsum[8];

    hsh[tid] = hidden[(size_t)token * Dim + tid];
    if (tid < ROWS)
        idsh[tid] = (tid == 0) ? target[token]
                               : noise[(size_t)token * Kk + (tid - 1)];
    __syncthreads();

    // 4 row streams per thread: r = warp*4 + g + 32*i
    const int r0 = warp * 4 + g;
    int  id[4];
    bool act[4];
    #pragma unroll
    for (int i = 0; i < 4; i++) {
        const int r = r0 + 32 * i;
        act[i] = (r < ROWS);
        id[i]  = act[i] ? idsh[r] : 0;
    }

    const float4* hv4 = reinterpret_cast<const float4*>(hsh);
    float s[4] = {0.f, 0.f, 0.f, 0.f};

    #pragma unroll
    for (int j = 0; j < 8; j++) {
        const float4 h = hv4[p + 8 * j];
        #pragma unroll
        for (int i = 0; i < 4; i++) {
            if (act[i]) {
                const float4 w = reinterpret_cast<const float4*>(
                        weight + (size_t)id[i] * Dim)[p + 8 * j];
                s[i] += h.x * w.x + h.y * w.y + h.z * w.z + h.w * w.w;
            }
        }
    }

    // reduce each stream across its 8-lane group
    #pragma unroll
    for (int i = 0; i < 4; i++) {
        s[i] += __shfl_xor_sync(0xFFFFFFFFu, s[i], 1);
        s[i] += __shfl_xor_sync(0xFFFFFFFFu, s[i], 2);
        s[i] += __shfl_xor_sync(0xFFFFFFFFu, s[i], 4);
    }

    float local = 0.0f;
    if (p == 0) {
        #pragma unroll
        for (int i = 0; i < 4; i++) {
            if (act[i]) {
                const int r = r0 + 32 * i;
                const float score = s[i] + bias[id[i]] - NORM_TERM;
                if (r == 0) {
                    local += fast_softplus(-(score - LOG_K));
                } else {
                    const float sn = __logf(noise_probs[id[i]]);
                    local += fast_softplus(score - sn - LOG_K);
                }
            }
        }
    }

    // warp reduce (nonzero only on lanes 0,8,16,24)
    #pragma unroll
    for (int o = 16; o > 0; o >>= 1)
        local += __shfl_xor_sync(0xFFFFFFFFu, local, o);

    if (lane == 0) wsum[warp] = local;
    __syncthreads();
    if (tid == 0) {
        float t = 0.0f;
        #pragma unroll
        for (int i = 0; i < 8; i++) t += wsum[i];
        atomicAdd(out, t * INV_NTOK);
    }
}

extern "C" void kernel_launch(void* const* d_in, const int* in_sizes, int n_in,
                              void* d_out, int out_size)
{
    const int*   target      = (const int*)  d_in[0];
    const int*   noise       = (const int*)  d_in[1];
    const float* hidden      = (const float*)d_in[2];
    const float* weight      = (const float*)d_in[3];
    const float* bias        = (const float*)d_in[4];
    const float* noise_probs = (const float*)d_in[5];
    float* out = (float*)d_out;

    zero_out_kernel<<<1, 1>>>(out);
    nce_loss_kernel<<<NTOK, 256>>>(target, noise, hidden, weight, bias,
                                   noise_probs, out);
}